// round 2
// baseline (speedup 1.0000x reference)
#include <cuda_runtime.h>

#define Bb 4
#define Tt 12
#define Nn 512
#define Dd 128
#define Ll 4
#define Hh 64

// ---------------- scratch (no allocation allowed) ----------------
__device__ float g_src[Bb * Nn * Dd];     // src_proj
__device__ float g_tgt[Bb * Nn * Dd];     // tgt_proj + bs1 folded in
__device__ float g_adj[Bb * Nn * Nn];     // thresholded adjacency
__device__ float g_a2 [Bb * Nn * Nn];     // adj @ adj
__device__ unsigned g_maxbits[Bb];        // per-batch max (float bits, all >= 0)

__global__ void k_init() {
    if (threadIdx.x < Bb) g_maxbits[threadIdx.x] = 0u;
}

// ---------------- stage 1: lag encoders + mean + projections ----------------
// grid: 128 blocks (16 (b,n)-rows each), 256 threads
__global__ __launch_bounds__(256) void k_encode(
    const float* __restrict__ x,
    const float* __restrict__ W1, const float* __restrict__ b1,
    const float* __restrict__ W2, const float* __restrict__ b2,
    const float* __restrict__ Ws1, const float* __restrict__ bs1)
{
    __shared__ float xl[16 * 512];   // [(r*4+l)*128 + d]; later reused as agg[r*128+d]
    __shared__ float hs[16 * 256];   // [r*256 + l*64 + j]

    int tid = threadIdx.x;
    int bn0 = blockIdx.x * 16;           // first global row (b*N + n)
    int b   = bn0 >> 9;
    int n0  = bn0 & (Nn - 1);

    // load 16 rows x 4 lags x 128
    #pragma unroll
    for (int i = 0; i < 32; i++) {
        int e  = tid + i * 256;
        int d  = e & 127;
        int rl = e >> 7;                  // r*4 + l
        int r  = rl >> 2, l = rl & 3;
        xl[e] = x[(((b * Tt) + (Tt - 1 - l)) * Nn + (n0 + r)) * Dd + d];
    }
    __syncthreads();

    // h[r][l][j] = relu(b1 + sum_d xl * W1)   (thread = one (l,j), 16 rows)
    {
        int l = tid >> 6, j = tid & 63;
        float acc[16];
        float bb = b1[l * Hh + j];
        #pragma unroll
        for (int r = 0; r < 16; r++) acc[r] = bb;
        const float* w1 = W1 + (size_t)l * Dd * Hh + j;
        for (int d = 0; d < Dd; d++) {
            float w = w1[d * Hh];
            #pragma unroll
            for (int r = 0; r < 16; r++)
                acc[r] = fmaf(xl[(r * 4 + l) * 128 + d], w, acc[r]);
        }
        #pragma unroll
        for (int r = 0; r < 16; r++)
            hs[r * 256 + tid] = fmaxf(acc[r], 0.f);
    }
    __syncthreads();

    // agg[r][d] = 0.25 * (sum_{l,j} h * W2) + 0.25 * sum_l b2   (thread = one d, 8 rows)
    {
        int d = tid & 127, halfr = tid >> 7;   // rows halfr*8 .. +7
        float bbar = 0.f;
        #pragma unroll
        for (int l = 0; l < Ll; l++) bbar += b2[l * Dd + d];
        bbar *= 0.25f;
        float acc[8];
        #pragma unroll
        for (int r = 0; r < 8; r++) acc[r] = 0.f;
        for (int o = 0; o < Ll * Hh; o++) {     // o = l*64+j, matches W2 flat layout
            float w = W2[(size_t)o * Dd + d];
            #pragma unroll
            for (int r = 0; r < 8; r++)
                acc[r] = fmaf(hs[(halfr * 8 + r) * 256 + o], w, acc[r]);
        }
        #pragma unroll
        for (int r = 0; r < 8; r++)
            xl[(halfr * 8 + r) * 128 + d] = fmaf(acc[r], 0.25f, bbar);  // reuse xl as agg
    }
    __syncthreads();

    // src/tgt projections  (thread = one output d, half selects src/tgt, 16 rows)
    {
        int dcol = tid & 127;
        int half = tid >> 7;                 // 0 = src, 1 = tgt
        float acc[16];
        float binit = half ? bs1[dcol] : 0.f;  // fold bs1 into tgt
        #pragma unroll
        for (int r = 0; r < 16; r++) acc[r] = binit;
        const float* ws = Ws1 + (size_t)half * Dd * Dd + dcol;
        for (int dd = 0; dd < Dd; dd++) {
            float w = ws[dd * Dd];
            #pragma unroll
            for (int r = 0; r < 16; r++)
                acc[r] = fmaf(xl[r * 128 + dd], w, acc[r]);
        }
        float* dst = half ? g_tgt : g_src;
        #pragma unroll
        for (int r = 0; r < 16; r++)
            dst[(size_t)(bn0 + r) * Dd + dcol] = acc[r];
    }
}

// ---------------- stage 2: pairwise scorer -> adjacency ----------------
// grid (16,16,4), block (8,32): threadIdx.y = ti, threadIdx.x covers 4 j's each
__global__ __launch_bounds__(256) void k_score(
    const float* __restrict__ Ws2, const float* __restrict__ bs2)
{
    __shared__ float st[32][129];
    __shared__ float tt[32][129];
    __shared__ float w[128];

    int b  = blockIdx.z;
    int i0 = blockIdx.y * 32, j0 = blockIdx.x * 32;
    int tid = threadIdx.y * 8 + threadIdx.x;

    for (int e = tid; e < 32 * 128; e += 256) {
        int r = e >> 7, c = e & 127;
        st[r][c] = g_src[(size_t)(b * Nn + i0 + r) * Dd + c];
        tt[r][c] = g_tgt[(size_t)(b * Nn + j0 + r) * Dd + c];
    }
    if (tid < 128) w[tid] = Ws2[tid];
    __syncthreads();

    int ti = threadIdx.y;
    int tjb = threadIdx.x << 2;           // 4 consecutive j per thread
    float acc0 = 0.f, acc1 = 0.f, acc2 = 0.f, acc3 = 0.f;
    #pragma unroll 4
    for (int d = 0; d < Dd; d++) {
        float s  = st[ti][d];
        float wv = w[d];
        acc0 = fmaf(fmaxf(s + tt[tjb + 0][d], 0.f), wv, acc0);
        acc1 = fmaf(fmaxf(s + tt[tjb + 1][d], 0.f), wv, acc1);
        acc2 = fmaf(fmaxf(s + tt[tjb + 2][d], 0.f), wv, acc2);
        acc3 = fmaf(fmaxf(s + tt[tjb + 3][d], 0.f), wv, acc3);
    }
    float bz = bs2[0];
    int i = i0 + ti;
    float accs[4] = {acc0, acc1, acc2, acc3};
    #pragma unroll
    for (int jj = 0; jj < 4; jj++) {
        int j = j0 + tjb + jj;
        float sc = 1.f / (1.f + __expf(-(accs[jj] + bz)));
        float a  = (sc > 0.1f && i != j) ? sc : 0.f;
        g_adj[((size_t)b * Nn + i) * Nn + j] = a;
    }
}

// ---------------- stage 3/4: batched GEMMs ----------------
// FUSE=0: a2 = adj @ adj.   FUSE=1: enhanced = adj + 0.5*a2 + 0.25*(a2@adj), + per-batch max
#define GBM 64
#define GBN 64
#define GBK 16

template <int FUSE>
__global__ __launch_bounds__(256) void k_gemm(float* __restrict__ dout)
{
    const float* A  = FUSE ? g_a2 : g_adj;
    const float* Bm = g_adj;
    float* C        = FUSE ? dout : g_a2;

    int b = blockIdx.z;
    const float* Ab = A  + (size_t)b * Nn * Nn;
    const float* Bp = Bm + (size_t)b * Nn * Nn;
    float* Cb       = C  + (size_t)b * Nn * Nn;

    __shared__ float As[GBM][GBK + 1];
    __shared__ float Bs[GBK][GBN];
    __shared__ float red[256];

    int tid = threadIdx.x;
    int tx = tid & 15, ty = tid >> 4;
    int m0 = blockIdx.y * GBM, n0 = blockIdx.x * GBN;

    float acc[4][4] = {};
    for (int k0 = 0; k0 < Nn; k0 += GBK) {
        #pragma unroll
        for (int e = 0; e < 4; e++) {
            int idx = tid + e * 256;
            As[idx >> 4][idx & 15] = Ab[(m0 + (idx >> 4)) * Nn + k0 + (idx & 15)];
            Bs[idx >> 6][idx & 63] = Bp[(k0 + (idx >> 6)) * Nn + n0 + (idx & 63)];
        }
        __syncthreads();
        #pragma unroll
        for (int k = 0; k < GBK; k++) {
            float4 bv = *reinterpret_cast<const float4*>(&Bs[k][tx << 2]);
            float av[4];
            #pragma unroll
            for (int i = 0; i < 4; i++) av[i] = As[(ty << 2) + i][k];
            float bvv[4] = {bv.x, bv.y, bv.z, bv.w};
            #pragma unroll
            for (int i = 0; i < 4; i++)
                #pragma unroll
                for (int j = 0; j < 4; j++)
                    acc[i][j] = fmaf(av[i], bvv[j], acc[i][j]);
        }
        __syncthreads();
    }

    float lmax = 0.f;
    #pragma unroll
    for (int i = 0; i < 4; i++) {
        int m = m0 + (ty << 2) + i;
        #pragma unroll
        for (int j = 0; j < 4; j++) {
            int nn = n0 + (tx << 2) + j;
            int off = m * Nn + nn;
            if (FUSE) {
                size_t goff = (size_t)b * Nn * Nn + off;
                float e = g_adj[goff] + 0.5f * g_a2[goff] + 0.25f * acc[i][j];
                Cb[off] = e;
                lmax = fmaxf(lmax, e);
            } else {
                Cb[off] = acc[i][j];
            }
        }
    }
    if (FUSE) {
        red[tid] = lmax;
        __syncthreads();
        #pragma unroll
        for (int s = 128; s > 0; s >>= 1) {
            if (tid < s) red[tid] = fmaxf(red[tid], red[tid + s]);
            __syncthreads();
        }
        if (tid == 0) atomicMax(&g_maxbits[b], __float_as_uint(red[0]));
    }
}

// ---------------- stage 5: normalize ----------------
__global__ void k_norm(float* __restrict__ out)
{
    int idx = blockIdx.x * 256 + threadIdx.x;     // B*N*N = 2^20 total
    int b = idx >> 18;                            // N*N = 2^18
    float mx = __uint_as_float(g_maxbits[b]);
    out[idx] = out[idx] / (mx + 1e-8f);
}

// ---------------- launch ----------------
extern "C" void kernel_launch(void* const* d_in, const int* in_sizes, int n_in,
                              void* d_out, int out_size)
{
    const float* x   = (const float*)d_in[0];
    const float* W1  = (const float*)d_in[1];
    const float* b1  = (const float*)d_in[2];
    const float* W2  = (const float*)d_in[3];
    const float* b2  = (const float*)d_in[4];
    const float* Ws1 = (const float*)d_in[5];
    const float* bs1 = (const float*)d_in[6];
    const float* Ws2 = (const float*)d_in[7];
    const float* bs2 = (const float*)d_in[8];
    float* out = (float*)d_out;

    k_init<<<1, 32>>>();
    k_encode<<<(Bb * Nn) / 16, 256>>>(x, W1, b1, W2, b2, Ws1, bs1);
    k_score<<<dim3(Nn / 32, Nn / 32, Bb), dim3(8, 32)>>>(Ws2, bs2);
    k_gemm<0><<<dim3(Nn / GBN, Nn / GBM, Bb), 256>>>(out);
    k_gemm<1><<<dim3(Nn / GBN, Nn / GBM, Bb), 256>>>(out);
    k_norm<<<(Bb * Nn * Nn) / 256, 256>>>(out);
}

// round 5
// speedup vs baseline: 1.4098x; 1.4098x over previous
#include <cuda_runtime.h>

#define Bb 4
#define Tt 12
#define Nn 512
#define Dd 128
#define Ll 4
#define Hh 64

// ---------------- scratch (no allocation allowed) ----------------
__device__ float g_src[Bb * Nn * Dd];     // src_proj
__device__ float g_tgt[Bb * Nn * Dd];     // tgt_proj + bs1 folded in
__device__ float g_adj[Bb * Nn * Nn];     // thresholded adjacency
__device__ float g_a2 [Bb * Nn * Nn];     // adj @ adj
__device__ unsigned g_maxbits[Bb];        // per-batch max (float bits, all >= 0)

__global__ void k_init() {
    if (threadIdx.x < Bb) g_maxbits[threadIdx.x] = 0u;
}

// ---------------- stage 1: lag encoders + mean + projections ----------------
__global__ __launch_bounds__(256) void k_encode(
    const float* __restrict__ x,
    const float* __restrict__ W1, const float* __restrict__ b1,
    const float* __restrict__ W2, const float* __restrict__ b2,
    const float* __restrict__ Ws1, const float* __restrict__ bs1)
{
    __shared__ float xl[16 * 512];   // [(r*4+l)*128 + d]; later reused as agg[r*128+d]
    __shared__ float hs[16 * 256];   // [r*256 + l*64 + j]

    int tid = threadIdx.x;
    int bn0 = blockIdx.x * 16;           // first global row (b*N + n)
    int b   = bn0 >> 9;
    int n0  = bn0 & (Nn - 1);

    #pragma unroll
    for (int i = 0; i < 32; i++) {
        int e  = tid + i * 256;
        int d  = e & 127;
        int rl = e >> 7;
        int r  = rl >> 2, l = rl & 3;
        xl[e] = x[(((b * Tt) + (Tt - 1 - l)) * Nn + (n0 + r)) * Dd + d];
    }
    __syncthreads();

    {
        int l = tid >> 6, j = tid & 63;
        float acc[16];
        float bb = b1[l * Hh + j];
        #pragma unroll
        for (int r = 0; r < 16; r++) acc[r] = bb;
        const float* w1 = W1 + (size_t)l * Dd * Hh + j;
        for (int d = 0; d < Dd; d++) {
            float w = w1[d * Hh];
            #pragma unroll
            for (int r = 0; r < 16; r++)
                acc[r] = fmaf(xl[(r * 4 + l) * 128 + d], w, acc[r]);
        }
        #pragma unroll
        for (int r = 0; r < 16; r++)
            hs[r * 256 + tid] = fmaxf(acc[r], 0.f);
    }
    __syncthreads();

    {
        int d = tid & 127, halfr = tid >> 7;
        float bbar = 0.f;
        #pragma unroll
        for (int l = 0; l < Ll; l++) bbar += b2[l * Dd + d];
        bbar *= 0.25f;
        float acc[8];
        #pragma unroll
        for (int r = 0; r < 8; r++) acc[r] = 0.f;
        for (int o = 0; o < Ll * Hh; o++) {
            float w = W2[(size_t)o * Dd + d];
            #pragma unroll
            for (int r = 0; r < 8; r++)
                acc[r] = fmaf(hs[(halfr * 8 + r) * 256 + o], w, acc[r]);
        }
        #pragma unroll
        for (int r = 0; r < 8; r++)
            xl[(halfr * 8 + r) * 128 + d] = fmaf(acc[r], 0.25f, bbar);
    }
    __syncthreads();

    {
        int dcol = tid & 127;
        int half = tid >> 7;                 // 0 = src, 1 = tgt
        float acc[16];
        float binit = half ? bs1[dcol] : 0.f;
        #pragma unroll
        for (int r = 0; r < 16; r++) acc[r] = binit;
        const float* ws = Ws1 + (size_t)half * Dd * Dd + dcol;
        for (int dd = 0; dd < Dd; dd++) {
            float w = ws[dd * Dd];
            #pragma unroll
            for (int r = 0; r < 16; r++)
                acc[r] = fmaf(xl[r * 128 + dd], w, acc[r]);
        }
        float* dst = half ? g_tgt : g_src;
        #pragma unroll
        for (int r = 0; r < 16; r++)
            dst[(size_t)(bn0 + r) * Dd + dcol] = acc[r];
    }
}

// ---------------- stage 2: pairwise scorer -> adjacency ----------------
__global__ __launch_bounds__(256) void k_score(
    const float* __restrict__ Ws2, const float* __restrict__ bs2)
{
    __shared__ float st[32][129];
    __shared__ float tt[32][129];
    __shared__ float w[128];

    int b  = blockIdx.z;
    int i0 = blockIdx.y * 32, j0 = blockIdx.x * 32;
    int tid = threadIdx.y * 8 + threadIdx.x;

    for (int e = tid; e < 32 * 128; e += 256) {
        int r = e >> 7, c = e & 127;
        st[r][c] = g_src[(size_t)(b * Nn + i0 + r) * Dd + c];
        tt[r][c] = g_tgt[(size_t)(b * Nn + j0 + r) * Dd + c];
    }
    if (tid < 128) w[tid] = Ws2[tid];
    __syncthreads();

    int ti = threadIdx.y;
    int tjb = threadIdx.x << 2;
    float acc0 = 0.f, acc1 = 0.f, acc2 = 0.f, acc3 = 0.f;
    #pragma unroll 4
    for (int d = 0; d < Dd; d++) {
        float s  = st[ti][d];
        float wv = w[d];
        acc0 = fmaf(fmaxf(s + tt[tjb + 0][d], 0.f), wv, acc0);
        acc1 = fmaf(fmaxf(s + tt[tjb + 1][d], 0.f), wv, acc1);
        acc2 = fmaf(fmaxf(s + tt[tjb + 2][d], 0.f), wv, acc2);
        acc3 = fmaf(fmaxf(s + tt[tjb + 3][d], 0.f), wv, acc3);
    }
    float bz = bs2[0];
    int i = i0 + ti;
    float accs[4] = {acc0, acc1, acc2, acc3};
    #pragma unroll
    for (int jj = 0; jj < 4; jj++) {
        int j = j0 + tjb + jj;
        float sc = 1.f / (1.f + __expf(-(accs[jj] + bz)));
        float a  = (sc > 0.1f && i != j) ? sc : 0.f;
        g_adj[((size_t)b * Nn + i) * Nn + j] = a;
    }
}

// ---------------- stage 3/4: batched TF32 tensor-core GEMMs ----------------
// FUSE=0: a2 = adj @ adj
// FUSE=1: out = adj + 0.5*a2 + 0.25*(a2 @ adj), plus per-batch max
#define TM 128
#define TN 64
#define TK 32
#define ASTR 36     // 36 mod 32 = 4  -> A-frag banks = 4*gid + tig : bijective
#define BSTR 72     // 72 mod 32 = 8  -> B-frag banks = 8*tig + gid : bijective

__device__ __forceinline__ unsigned f2tf32(float x) {
    unsigned r;
    asm("cvt.rna.tf32.f32 %0, %1;" : "=r"(r) : "f"(x));
    return r;
}

__device__ __forceinline__ void mma_tf32(float* d, const unsigned* a,
                                         const unsigned* b, const float* c) {
    asm volatile(
        "mma.sync.aligned.m16n8k8.row.col.f32.tf32.tf32.f32 "
        "{%0,%1,%2,%3}, {%4,%5,%6,%7}, {%8,%9}, {%10,%11,%12,%13};\n"
        : "=f"(d[0]), "=f"(d[1]), "=f"(d[2]), "=f"(d[3])
        : "r"(a[0]), "r"(a[1]), "r"(a[2]), "r"(a[3]),
          "r"(b[0]), "r"(b[1]),
          "f"(c[0]), "f"(c[1]), "f"(c[2]), "f"(c[3]));
}

template <int FUSE>
__global__ __launch_bounds__(256) void k_mma(float* __restrict__ dout)
{
    const float* A  = FUSE ? g_a2 : g_adj;
    const float* Bm = g_adj;
    float* C        = FUSE ? dout : g_a2;

    int b = blockIdx.z;
    const float* Ab = A  + (size_t)b * Nn * Nn;
    const float* Bp = Bm + (size_t)b * Nn * Nn;
    float* Cb       = C  + (size_t)b * Nn * Nn;

    __shared__ float As[TM * ASTR];
    __shared__ float Bs[TK * BSTR];
    __shared__ float wmax[8];

    int tid  = threadIdx.x;
    int m0   = blockIdx.y * TM, n0 = blockIdx.x * TN;
    int warpId = tid >> 5, lane = tid & 31;
    int wm  = (warpId & 3) * 32;          // warp row offset in tile
    int wn  = (warpId >> 2) * 32;         // warp col offset in tile
    int gid = lane >> 2, tig = lane & 3;

    // staging indices: A tile 128x32 (8 float4 per row), B tile 32x64 (16 float4 per row)
    int arow = tid >> 3, ac4 = (tid & 7) * 4;     // +p*32 rows, p=0..3
    int brow = tid >> 4, bc4 = (tid & 15) * 4;    // +p*16 rows, p=0..1

    const float* agp = Ab + (size_t)(m0 + arow) * Nn + ac4;
    const float* bgp = Bp + (size_t)brow * Nn + n0 + bc4;

    float4 ra[4], rb[2];
    #pragma unroll
    for (int p = 0; p < 4; p++) ra[p] = *(const float4*)(agp + p * 32 * Nn);
    #pragma unroll
    for (int p = 0; p < 2; p++) rb[p] = *(const float4*)(bgp + p * 16 * Nn);

    float acc[2][4][4];
    #pragma unroll
    for (int i = 0; i < 2; i++)
        #pragma unroll
        for (int j = 0; j < 4; j++)
            #pragma unroll
            for (int r = 0; r < 4; r++) acc[i][j][r] = 0.f;

    for (int k0 = 0; k0 < Nn; k0 += TK) {
        // stage to smem with RNA tf32 rounding (unbiased)
        #pragma unroll
        for (int p = 0; p < 4; p++) {
            float4 t;
            t.x = __uint_as_float(f2tf32(ra[p].x));
            t.y = __uint_as_float(f2tf32(ra[p].y));
            t.z = __uint_as_float(f2tf32(ra[p].z));
            t.w = __uint_as_float(f2tf32(ra[p].w));
            *(float4*)(As + (arow + p * 32) * ASTR + ac4) = t;
        }
        #pragma unroll
        for (int p = 0; p < 2; p++) {
            float4 t;
            t.x = __uint_as_float(f2tf32(rb[p].x));
            t.y = __uint_as_float(f2tf32(rb[p].y));
            t.z = __uint_as_float(f2tf32(rb[p].z));
            t.w = __uint_as_float(f2tf32(rb[p].w));
            *(float4*)(Bs + (brow + p * 16) * BSTR + bc4) = t;
        }
        __syncthreads();

        // prefetch next k-panel while mma runs
        if (k0 + TK < Nn) {
            #pragma unroll
            for (int p = 0; p < 4; p++)
                ra[p] = *(const float4*)(agp + (k0 + TK) + p * 32 * Nn);
            #pragma unroll
            for (int p = 0; p < 2; p++)
                rb[p] = *(const float4*)(bgp + (size_t)(k0 + TK) * Nn + p * 16 * Nn);
        }

        #pragma unroll
        for (int ks = 0; ks < 4; ks++) {
            int kb = ks * 8;
            unsigned af[2][4], bf[4][2];
            #pragma unroll
            for (int mt = 0; mt < 2; mt++) {
                int r0 = wm + mt * 16 + gid;
                af[mt][0] = __float_as_uint(As[r0 * ASTR + kb + tig]);
                af[mt][1] = __float_as_uint(As[(r0 + 8) * ASTR + kb + tig]);
                af[mt][2] = __float_as_uint(As[r0 * ASTR + kb + tig + 4]);
                af[mt][3] = __float_as_uint(As[(r0 + 8) * ASTR + kb + tig + 4]);
            }
            #pragma unroll
            for (int nt = 0; nt < 4; nt++) {
                int c0 = wn + nt * 8 + gid;
                bf[nt][0] = __float_as_uint(Bs[(kb + tig) * BSTR + c0]);
                bf[nt][1] = __float_as_uint(Bs[(kb + tig + 4) * BSTR + c0]);
            }
            #pragma unroll
            for (int mt = 0; mt < 2; mt++)
                #pragma unroll
                for (int nt = 0; nt < 4; nt++)
                    mma_tf32(acc[mt][nt], af[mt], bf[nt], acc[mt][nt]);
        }
        __syncthreads();
    }

    // epilogue: c0,c1 -> (row, 2t/2t+1), c2,c3 -> (row+8, ...)
    float lmax = 0.f;
    #pragma unroll
    for (int mt = 0; mt < 2; mt++) {
        #pragma unroll
        for (int nt = 0; nt < 4; nt++) {
            int row = m0 + wm + mt * 16 + gid;
            int col = n0 + wn + nt * 8 + 2 * tig;
            #pragma unroll
            for (int h = 0; h < 2; h++) {      // h=0: row, h=1: row+8
                int r = row + h * 8;
                int off = r * Nn + col;
                float v0 = acc[mt][nt][2 * h + 0];
                float v1 = acc[mt][nt][2 * h + 1];
                if (FUSE) {
                    size_t g = (size_t)b * Nn * Nn + off;
                    float e0 = g_adj[g]     + 0.5f * g_a2[g]     + 0.25f * v0;
                    float e1 = g_adj[g + 1] + 0.5f * g_a2[g + 1] + 0.25f * v1;
                    *(float2*)(Cb + off) = make_float2(e0, e1);
                    lmax = fmaxf(lmax, fmaxf(e0, e1));
                } else {
                    *(float2*)(Cb + off) = make_float2(v0, v1);
                }
            }
        }
    }
    if (FUSE) {
        #pragma unroll
        for (int s = 16; s > 0; s >>= 1)
            lmax = fmaxf(lmax, __shfl_xor_sync(0xFFFFFFFFu, lmax, s));
        if (lane == 0) wmax[warpId] = lmax;
        __syncthreads();
        if (tid == 0) {
            float m = wmax[0];
            #pragma unroll
            for (int i = 1; i < 8; i++) m = fmaxf(m, wmax[i]);
            atomicMax(&g_maxbits[b], __float_as_uint(m));
        }
    }
}

// ---------------- stage 5: normalize ----------------
__global__ void k_norm(float* __restrict__ out)
{
    int idx = blockIdx.x * 256 + threadIdx.x;
    int b = idx >> 18;
    float mx = __uint_as_float(g_maxbits[b]);
    out[idx] = out[idx] / (mx + 1e-8f);
}

// ---------------- launch ----------------
extern "C" void kernel_launch(void* const* d_in, const int* in_sizes, int n_in,
                              void* d_out, int out_size)
{
    const float* x   = (const float*)d_in[0];
    const float* W1  = (const float*)d_in[1];
    const float* b1  = (const float*)d_in[2];
    const float* W2  = (const float*)d_in[3];
    const float* b2  = (const float*)d_in[4];
    const float* Ws1 = (const float*)d_in[5];
    const float* bs1 = (const float*)d_in[6];
    const float* Ws2 = (const float*)d_in[7];
    const float* bs2 = (const float*)d_in[8];
    float* out = (float*)d_out;

    k_init<<<1, 32>>>();
    k_encode<<<(Bb * Nn) / 16, 256>>>(x, W1, b1, W2, b2, Ws1, bs1);
    k_score<<<dim3(Nn / 32, Nn / 32, Bb), dim3(8, 32)>>>(Ws2, bs2);
    k_mma<0><<<dim3(Nn / TN, Nn / TM, Bb), 256>>>(out);
    k_mma<1><<<dim3(Nn / TN, Nn / TM, Bb), 256>>>(out);
    k_norm<<<(Bb * Nn * Nn) / 256, 256>>>(out);
}

// round 7
// speedup vs baseline: 1.5087x; 1.0701x over previous
#include <cuda_runtime.h>

#define Bb 4
#define Tt 12
#define Nn 512
#define Dd 128
#define Ll 4
#define Hh 64

// ---------------- scratch (no allocation allowed) ----------------
__device__ float g_src[Bb * Nn * Dd];     // src_proj
__device__ float g_tgt[Bb * Nn * Dd];     // tgt_proj + bs1 folded in
__device__ float g_adj[Bb * Nn * Nn];     // thresholded adjacency
__device__ float g_a2 [Bb * Nn * Nn];     // adj @ adj
__device__ unsigned g_maxbits[Bb];        // per-batch max (float bits, all >= 0)

// ---------------- stage 1: lag encoders + mean + projections ----------------
__global__ __launch_bounds__(256) void k_encode(
    const float* __restrict__ x,
    const float* __restrict__ W1, const float* __restrict__ b1,
    const float* __restrict__ W2, const float* __restrict__ b2,
    const float* __restrict__ Ws1, const float* __restrict__ bs1)
{
    __shared__ float xl[16 * 512];   // [(r*4+l)*128 + d]; later reused as agg[r*128+d]
    __shared__ float hs[16 * 256];   // [r*256 + l*64 + j]

    int tid = threadIdx.x;
    if (blockIdx.x == 0 && tid < Bb) g_maxbits[tid] = 0u;   // folded k_init

    int bn0 = blockIdx.x * 16;           // first global row (b*N + n)
    int b   = bn0 >> 9;
    int n0  = bn0 & (Nn - 1);

    #pragma unroll
    for (int i = 0; i < 32; i++) {
        int e  = tid + i * 256;
        int d  = e & 127;
        int rl = e >> 7;
        int r  = rl >> 2, l = rl & 3;
        xl[e] = x[(((b * Tt) + (Tt - 1 - l)) * Nn + (n0 + r)) * Dd + d];
    }
    __syncthreads();

    {
        int l = tid >> 6, j = tid & 63;
        float acc[16];
        float bb = b1[l * Hh + j];
        #pragma unroll
        for (int r = 0; r < 16; r++) acc[r] = bb;
        const float* w1 = W1 + (size_t)l * Dd * Hh + j;
        for (int d = 0; d < Dd; d++) {
            float w = w1[d * Hh];
            #pragma unroll
            for (int r = 0; r < 16; r++)
                acc[r] = fmaf(xl[(r * 4 + l) * 128 + d], w, acc[r]);
        }
        #pragma unroll
        for (int r = 0; r < 16; r++)
            hs[r * 256 + tid] = fmaxf(acc[r], 0.f);
    }
    __syncthreads();

    {
        int d = tid & 127, halfr = tid >> 7;
        float bbar = 0.f;
        #pragma unroll
        for (int l = 0; l < Ll; l++) bbar += b2[l * Dd + d];
        bbar *= 0.25f;
        float acc[8];
        #pragma unroll
        for (int r = 0; r < 8; r++) acc[r] = 0.f;
        for (int o = 0; o < Ll * Hh; o++) {
            float w = W2[(size_t)o * Dd + d];
            #pragma unroll
            for (int r = 0; r < 8; r++)
                acc[r] = fmaf(hs[(halfr * 8 + r) * 256 + o], w, acc[r]);
        }
        #pragma unroll
        for (int r = 0; r < 8; r++)
            xl[(halfr * 8 + r) * 128 + d] = fmaf(acc[r], 0.25f, bbar);
    }
    __syncthreads();

    {
        int dcol = tid & 127;
        int half = tid >> 7;                 // 0 = src, 1 = tgt
        float acc[16];
        float binit = half ? bs1[dcol] : 0.f;
        #pragma unroll
        for (int r = 0; r < 16; r++) acc[r] = binit;
        const float* ws = Ws1 + (size_t)half * Dd * Dd + dcol;
        for (int dd = 0; dd < Dd; dd++) {
            float w = ws[dd * Dd];
            #pragma unroll
            for (int r = 0; r < 16; r++)
                acc[r] = fmaf(xl[r * 128 + dd], w, acc[r]);
        }
        float* dst = half ? g_tgt : g_src;
        #pragma unroll
        for (int r = 0; r < 16; r++)
            dst[(size_t)(bn0 + r) * Dd + dcol] = acc[r];
    }
}

// ---------------- stage 2: pairwise scorer -> adjacency ----------------
// block (8,32): ti = threadIdx.y, threadIdx.x covers 4 j's; 4 d's per iter (float4)
__global__ __launch_bounds__(256) void k_score(
    const float* __restrict__ Ws2, const float* __restrict__ bs2)
{
    __shared__ float st [32][132];   // [i][d], float4 loads (132*4 % 16 == 0)
    __shared__ float ttT[128][36];   // [d][j], float4 over j: conflict-free
    __shared__ float w4[128];

    int b  = blockIdx.z;
    int i0 = blockIdx.y * 32, j0 = blockIdx.x * 32;
    int tid = threadIdx.y * 8 + threadIdx.x;

    for (int e = tid; e < 32 * 128; e += 256) {
        int r = e >> 7, c = e & 127;
        st[r][c]  = g_src[(size_t)(b * Nn + i0 + r) * Dd + c];
        ttT[c][r] = g_tgt[(size_t)(b * Nn + j0 + r) * Dd + c];
    }
    if (tid < 128) w4[tid] = Ws2[tid];
    __syncthreads();

    int ti  = threadIdx.y;
    int tjb = threadIdx.x << 2;
    float a0 = 0.f, a1 = 0.f, a2 = 0.f, a3 = 0.f;
    #pragma unroll 8
    for (int d = 0; d < Dd; d += 4) {
        float4 sv = *(const float4*)&st[ti][d];
        float4 wv = *(const float4*)&w4[d];
        float4 t0 = *(const float4*)&ttT[d + 0][tjb];
        float4 t1 = *(const float4*)&ttT[d + 1][tjb];
        float4 t2 = *(const float4*)&ttT[d + 2][tjb];
        float4 t3 = *(const float4*)&ttT[d + 3][tjb];
        a0 = fmaf(fmaxf(sv.x + t0.x, 0.f), wv.x, a0);
        a1 = fmaf(fmaxf(sv.x + t0.y, 0.f), wv.x, a1);
        a2 = fmaf(fmaxf(sv.x + t0.z, 0.f), wv.x, a2);
        a3 = fmaf(fmaxf(sv.x + t0.w, 0.f), wv.x, a3);
        a0 = fmaf(fmaxf(sv.y + t1.x, 0.f), wv.y, a0);
        a1 = fmaf(fmaxf(sv.y + t1.y, 0.f), wv.y, a1);
        a2 = fmaf(fmaxf(sv.y + t1.z, 0.f), wv.y, a2);
        a3 = fmaf(fmaxf(sv.y + t1.w, 0.f), wv.y, a3);
        a0 = fmaf(fmaxf(sv.z + t2.x, 0.f), wv.z, a0);
        a1 = fmaf(fmaxf(sv.z + t2.y, 0.f), wv.z, a1);
        a2 = fmaf(fmaxf(sv.z + t2.z, 0.f), wv.z, a2);
        a3 = fmaf(fmaxf(sv.z + t2.w, 0.f), wv.z, a3);
        a0 = fmaf(fmaxf(sv.w + t3.x, 0.f), wv.w, a0);
        a1 = fmaf(fmaxf(sv.w + t3.y, 0.f), wv.w, a1);
        a2 = fmaf(fmaxf(sv.w + t3.z, 0.f), wv.w, a2);
        a3 = fmaf(fmaxf(sv.w + t3.w, 0.f), wv.w, a3);
    }
    float bz = bs2[0];
    int i = i0 + ti;
    float accs[4] = {a0, a1, a2, a3};
    #pragma unroll
    for (int jj = 0; jj < 4; jj++) {
        int j = j0 + tjb + jj;
        float sc = 1.f / (1.f + __expf(-(accs[jj] + bz)));
        float a  = (sc > 0.1f && i != j) ? sc : 0.f;
        g_adj[((size_t)b * Nn + i) * Nn + j] = a;
    }
}

// ---------------- stage 3/4: batched TF32 tensor-core GEMMs ----------------
// FUSE=0: a2 = adj @ adj
// FUSE=1: out = adj + 0.5*a2 + 0.25*(a2 @ adj), plus per-batch max
// 64x64x32 tiles, 256 CTAs, double-buffered smem (1 barrier / k-iter)
#define TM 64
#define TN 64
#define TK 32
#define ASTR 36     // A-frag banks 4*gid + tig : bijective
#define BSTR 72     // B-frag banks 8*tig + gid : bijective

__device__ __forceinline__ unsigned f2tf32(float x) {
    unsigned r;
    asm("cvt.rna.tf32.f32 %0, %1;" : "=r"(r) : "f"(x));
    return r;
}

__device__ __forceinline__ void mma_tf32(float* d, const unsigned* a,
                                         const unsigned* b, const float* c) {
    asm volatile(
        "mma.sync.aligned.m16n8k8.row.col.f32.tf32.tf32.f32 "
        "{%0,%1,%2,%3}, {%4,%5,%6,%7}, {%8,%9}, {%10,%11,%12,%13};\n"
        : "=f"(d[0]), "=f"(d[1]), "=f"(d[2]), "=f"(d[3])
        : "r"(a[0]), "r"(a[1]), "r"(a[2]), "r"(a[3]),
          "r"(b[0]), "r"(b[1]),
          "f"(c[0]), "f"(c[1]), "f"(c[2]), "f"(c[3]));
}

template <int FUSE>
__global__ __launch_bounds__(256) void k_mma(float* __restrict__ dout)
{
    const float* A  = FUSE ? g_a2 : g_adj;
    const float* Bm = g_adj;
    float* C        = FUSE ? dout : g_a2;

    int b = blockIdx.z;
    const float* Ab = A  + (size_t)b * Nn * Nn;
    const float* Bp = Bm + (size_t)b * Nn * Nn;
    float* Cb       = C  + (size_t)b * Nn * Nn;

    __shared__ float As[2][TM * ASTR];
    __shared__ float Bs[2][TK * BSTR];
    __shared__ float wmax[8];

    int tid  = threadIdx.x;
    int m0   = blockIdx.y * TM, n0 = blockIdx.x * TN;
    int warpId = tid >> 5, lane = tid & 31;
    int wm  = (warpId & 1) * 32;          // warp row offset
    int wn  = (warpId >> 1) * 16;         // warp col offset
    int gid = lane >> 2, tig = lane & 3;

    // staging: A tile 64x32, B tile 32x64; 2 float4 per thread each
    int arow = tid >> 3, ac4 = (tid & 7) * 4;     // rows arow, arow+32
    int brow = tid >> 4, bc4 = (tid & 15) * 4;    // rows brow, brow+16

    const float* agp = Ab + (size_t)(m0 + arow) * Nn + ac4;
    const float* bgp = Bp + (size_t)brow * Nn + n0 + bc4;

    float4 ra[2], rb[2];
    ra[0] = *(const float4*)(agp);
    ra[1] = *(const float4*)(agp + 32 * Nn);
    rb[0] = *(const float4*)(bgp);
    rb[1] = *(const float4*)(bgp + 16 * Nn);

    // stage buffer 0
    #pragma unroll
    for (int p = 0; p < 2; p++) {
        float4 t;
        t.x = __uint_as_float(f2tf32(ra[p].x));
        t.y = __uint_as_float(f2tf32(ra[p].y));
        t.z = __uint_as_float(f2tf32(ra[p].z));
        t.w = __uint_as_float(f2tf32(ra[p].w));
        *(float4*)(As[0] + (arow + p * 32) * ASTR + ac4) = t;
        float4 u;
        u.x = __uint_as_float(f2tf32(rb[p].x));
        u.y = __uint_as_float(f2tf32(rb[p].y));
        u.z = __uint_as_float(f2tf32(rb[p].z));
        u.w = __uint_as_float(f2tf32(rb[p].w));
        *(float4*)(Bs[0] + (brow + p * 16) * BSTR + bc4) = u;
    }
    __syncthreads();

    float acc[2][2][4];
    #pragma unroll
    for (int i = 0; i < 2; i++)
        #pragma unroll
        for (int j = 0; j < 2; j++)
            #pragma unroll
            for (int r = 0; r < 4; r++) acc[i][j][r] = 0.f;

    #pragma unroll 1
    for (int kt = 0; kt < Nn / TK; kt++) {
        int cur = kt & 1;
        if (kt < Nn / TK - 1) {                       // prefetch next panel
            int k0 = (kt + 1) * TK;
            ra[0] = *(const float4*)(agp + k0);
            ra[1] = *(const float4*)(agp + k0 + 32 * Nn);
            rb[0] = *(const float4*)(bgp + (size_t)k0 * Nn);
            rb[1] = *(const float4*)(bgp + (size_t)k0 * Nn + 16 * Nn);
        }

        const float* Ac = As[cur];
        const float* Bc = Bs[cur];
        #pragma unroll
        for (int ks = 0; ks < 4; ks++) {
            int kb = ks * 8;
            unsigned af[2][4], bf[2][2];
            #pragma unroll
            for (int mt = 0; mt < 2; mt++) {
                int r0 = wm + mt * 16 + gid;
                af[mt][0] = __float_as_uint(Ac[r0 * ASTR + kb + tig]);
                af[mt][1] = __float_as_uint(Ac[(r0 + 8) * ASTR + kb + tig]);
                af[mt][2] = __float_as_uint(Ac[r0 * ASTR + kb + tig + 4]);
                af[mt][3] = __float_as_uint(Ac[(r0 + 8) * ASTR + kb + tig + 4]);
            }
            #pragma unroll
            for (int nt = 0; nt < 2; nt++) {
                int c0 = wn + nt * 8 + gid;
                bf[nt][0] = __float_as_uint(Bc[(kb + tig) * BSTR + c0]);
                bf[nt][1] = __float_as_uint(Bc[(kb + tig + 4) * BSTR + c0]);
            }
            #pragma unroll
            for (int mt = 0; mt < 2; mt++)
                #pragma unroll
                for (int nt = 0; nt < 2; nt++)
                    mma_tf32(acc[mt][nt], af[mt], bf[nt], acc[mt][nt]);
        }

        if (kt < Nn / TK - 1) {                       // store into other buffer
            int nxt = cur ^ 1;
            #pragma unroll
            for (int p = 0; p < 2; p++) {
                float4 t;
                t.x = __uint_as_float(f2tf32(ra[p].x));
                t.y = __uint_as_float(f2tf32(ra[p].y));
                t.z = __uint_as_float(f2tf32(ra[p].z));
                t.w = __uint_as_float(f2tf32(ra[p].w));
                *(float4*)(As[nxt] + (arow + p * 32) * ASTR + ac4) = t;
                float4 u;
                u.x = __uint_as_float(f2tf32(rb[p].x));
                u.y = __uint_as_float(f2tf32(rb[p].y));
                u.z = __uint_as_float(f2tf32(rb[p].z));
                u.w = __uint_as_float(f2tf32(rb[p].w));
                *(float4*)(Bs[nxt] + (brow + p * 16) * BSTR + bc4) = u;
            }
        }
        __syncthreads();
    }

    // epilogue: c0,c1 -> (row, 2t/2t+1), c2,c3 -> (row+8, ...)
    float lmax = 0.f;
    #pragma unroll
    for (int mt = 0; mt < 2; mt++) {
        #pragma unroll
        for (int nt = 0; nt < 2; nt++) {
            int row = m0 + wm + mt * 16 + gid;
            int col = n0 + wn + nt * 8 + 2 * tig;
            #pragma unroll
            for (int h = 0; h < 2; h++) {
                int r = row + h * 8;
                int off = r * Nn + col;
                float v0 = acc[mt][nt][2 * h + 0];
                float v1 = acc[mt][nt][2 * h + 1];
                if (FUSE) {
                    size_t g = (size_t)b * Nn * Nn + off;
                    float e0 = g_adj[g]     + 0.5f * g_a2[g]     + 0.25f * v0;
                    float e1 = g_adj[g + 1] + 0.5f * g_a2[g + 1] + 0.25f * v1;
                    *(float2*)(Cb + off) = make_float2(e0, e1);
                    lmax = fmaxf(lmax, fmaxf(e0, e1));
                } else {
                    *(float2*)(Cb + off) = make_float2(v0, v1);
                }
            }
        }
    }
    if (FUSE) {
        #pragma unroll
        for (int s = 16; s > 0; s >>= 1)
            lmax = fmaxf(lmax, __shfl_xor_sync(0xFFFFFFFFu, lmax, s));
        if (lane == 0) wmax[warpId] = lmax;
        __syncthreads();
        if (tid == 0) {
            float m = wmax[0];
            #pragma unroll
            for (int i = 1; i < 8; i++) m = fmaxf(m, wmax[i]);
            atomicMax(&g_maxbits[b], __float_as_uint(m));
        }
    }
}

// ---------------- stage 5: normalize (float4) ----------------
__global__ void k_norm(float* __restrict__ out)
{
    int idx = blockIdx.x * 256 + threadIdx.x;     // B*N*N/4 threads
    int b = idx >> 16;                            // (N*N/4) = 2^16 per batch
    float mx = __uint_as_float(g_maxbits[b]);
    float inv = 1.f / (mx + 1e-8f);
    float4 v = ((const float4*)out)[idx];
    v.x *= inv; v.y *= inv; v.z *= inv; v.w *= inv;
    ((float4*)out)[idx] = v;
}

// ---------------- launch ----------------
extern "C" void kernel_launch(void* const* d_in, const int* in_sizes, int n_in,
                              void* d_out, int out_size)
{
    const float* x   = (const float*)d_in[0];
    const float* W1  = (const float*)d_in[1];
    const float* b1  = (const float*)d_in[2];
    const float* W2  = (const float*)d_in[3];
    const float* b2  = (const float*)d_in[4];
    const float* Ws1 = (const float*)d_in[5];
    const float* bs1 = (const float*)d_in[6];
    const float* Ws2 = (const float*)d_in[7];
    const float* bs2 = (const float*)d_in[8];
    float* out = (float*)d_out;

    k_encode<<<(Bb * Nn) / 16, 256>>>(x, W1, b1, W2, b2, Ws1, bs1);
    k_score<<<dim3(Nn / 32, Nn / 32, Bb), dim3(8, 32)>>>(Ws2, bs2);
    k_mma<0><<<dim3(Nn / TN, Nn / TM, Bb), 256>>>(out);
    k_mma<1><<<dim3(Nn / TN, Nn / TM, Bb), 256>>>(out);
    k_norm<<<(Bb * Nn * Nn) / 1024, 256>>>(out);
}

// round 8
// speedup vs baseline: 1.5329x; 1.0161x over previous
#include <cuda_runtime.h>

#define Bb 4
#define Tt 12
#define Nn 512
#define Dd 128
#define Ll 4
#define Hh 64

// ---------------- scratch (no allocation allowed) ----------------
__device__ float g_src[Bb * Nn * Dd];     // src_proj
__device__ float g_tgt[Bb * Nn * Dd];     // tgt_proj + bs1 folded in
__device__ float g_adj[Bb * Nn * Nn];     // thresholded adjacency
__device__ float g_p0[Bb * Nn * Nn];      // a2 partial (k-half 0)
__device__ float g_p1[Bb * Nn * Nn];      // a2 partial (k-half 1)
__device__ float g_q0[Bb * Nn * Nn];      // a3 partial (k-half 0)
__device__ float g_q1[Bb * Nn * Nn];      // a3 partial (k-half 1)
__device__ unsigned g_maxbits[Bb];        // per-batch max (float bits, all >= 0)

// ---------------- stage 1: lag encoders + mean + projections ----------------
__global__ __launch_bounds__(256) void k_encode(
    const float* __restrict__ x,
    const float* __restrict__ W1, const float* __restrict__ b1,
    const float* __restrict__ W2, const float* __restrict__ b2,
    const float* __restrict__ Ws1, const float* __restrict__ bs1)
{
    __shared__ float xl[16 * 512];   // [(r*4+l)*128 + d]; later reused as agg[r*128+d]
    __shared__ float hs[16 * 256];   // [r*256 + l*64 + j]

    int tid = threadIdx.x;
    if (blockIdx.x == 0 && tid < Bb) g_maxbits[tid] = 0u;   // folded k_init

    int bn0 = blockIdx.x * 16;           // first global row (b*N + n)
    int b   = bn0 >> 9;
    int n0  = bn0 & (Nn - 1);

    #pragma unroll
    for (int i = 0; i < 32; i++) {
        int e  = tid + i * 256;
        int d  = e & 127;
        int rl = e >> 7;
        int r  = rl >> 2, l = rl & 3;
        xl[e] = x[(((b * Tt) + (Tt - 1 - l)) * Nn + (n0 + r)) * Dd + d];
    }
    __syncthreads();

    {
        int l = tid >> 6, j = tid & 63;
        float acc[16];
        float bb = b1[l * Hh + j];
        #pragma unroll
        for (int r = 0; r < 16; r++) acc[r] = bb;
        const float* w1 = W1 + (size_t)l * Dd * Hh + j;
        for (int d = 0; d < Dd; d++) {
            float w = w1[d * Hh];
            #pragma unroll
            for (int r = 0; r < 16; r++)
                acc[r] = fmaf(xl[(r * 4 + l) * 128 + d], w, acc[r]);
        }
        #pragma unroll
        for (int r = 0; r < 16; r++)
            hs[r * 256 + tid] = fmaxf(acc[r], 0.f);
    }
    __syncthreads();

    {
        int d = tid & 127, halfr = tid >> 7;
        float bbar = 0.f;
        #pragma unroll
        for (int l = 0; l < Ll; l++) bbar += b2[l * Dd + d];
        bbar *= 0.25f;
        float acc[8];
        #pragma unroll
        for (int r = 0; r < 8; r++) acc[r] = 0.f;
        for (int o = 0; o < Ll * Hh; o++) {
            float w = W2[(size_t)o * Dd + d];
            #pragma unroll
            for (int r = 0; r < 8; r++)
                acc[r] = fmaf(hs[(halfr * 8 + r) * 256 + o], w, acc[r]);
        }
        #pragma unroll
        for (int r = 0; r < 8; r++)
            xl[(halfr * 8 + r) * 128 + d] = fmaf(acc[r], 0.25f, bbar);
    }
    __syncthreads();

    {
        int dcol = tid & 127;
        int half = tid >> 7;                 // 0 = src, 1 = tgt
        float acc[16];
        float binit = half ? bs1[dcol] : 0.f;
        #pragma unroll
        for (int r = 0; r < 16; r++) acc[r] = binit;
        const float* ws = Ws1 + (size_t)half * Dd * Dd + dcol;
        for (int dd = 0; dd < Dd; dd++) {
            float w = ws[dd * Dd];
            #pragma unroll
            for (int r = 0; r < 16; r++)
                acc[r] = fmaf(xl[r * 128 + dd], w, acc[r]);
        }
        float* dst = half ? g_tgt : g_src;
        #pragma unroll
        for (int r = 0; r < 16; r++)
            dst[(size_t)(bn0 + r) * Dd + dcol] = acc[r];
    }
}

// ---------------- stage 2: pairwise scorer -> adjacency ----------------
__global__ __launch_bounds__(256) void k_score(
    const float* __restrict__ Ws2, const float* __restrict__ bs2)
{
    __shared__ float st [32][132];   // [i][d], float4 loads
    __shared__ float ttT[128][36];   // [d][j], float4 over j: conflict-free
    __shared__ float w4[128];

    int b  = blockIdx.z;
    int i0 = blockIdx.y * 32, j0 = blockIdx.x * 32;
    int tid = threadIdx.y * 8 + threadIdx.x;

    for (int e = tid; e < 32 * 128; e += 256) {
        int r = e >> 7, c = e & 127;
        st[r][c]  = g_src[(size_t)(b * Nn + i0 + r) * Dd + c];
        ttT[c][r] = g_tgt[(size_t)(b * Nn + j0 + r) * Dd + c];
    }
    if (tid < 128) w4[tid] = Ws2[tid];
    __syncthreads();

    int ti  = threadIdx.y;
    int tjb = threadIdx.x << 2;
    float a0 = 0.f, a1 = 0.f, a2 = 0.f, a3 = 0.f;
    #pragma unroll 8
    for (int d = 0; d < Dd; d += 4) {
        float4 sv = *(const float4*)&st[ti][d];
        float4 wv = *(const float4*)&w4[d];
        float4 t0 = *(const float4*)&ttT[d + 0][tjb];
        float4 t1 = *(const float4*)&ttT[d + 1][tjb];
        float4 t2 = *(const float4*)&ttT[d + 2][tjb];
        float4 t3 = *(const float4*)&ttT[d + 3][tjb];
        a0 = fmaf(fmaxf(sv.x + t0.x, 0.f), wv.x, a0);
        a1 = fmaf(fmaxf(sv.x + t0.y, 0.f), wv.x, a1);
        a2 = fmaf(fmaxf(sv.x + t0.z, 0.f), wv.x, a2);
        a3 = fmaf(fmaxf(sv.x + t0.w, 0.f), wv.x, a3);
        a0 = fmaf(fmaxf(sv.y + t1.x, 0.f), wv.y, a0);
        a1 = fmaf(fmaxf(sv.y + t1.y, 0.f), wv.y, a1);
        a2 = fmaf(fmaxf(sv.y + t1.z, 0.f), wv.y, a2);
        a3 = fmaf(fmaxf(sv.y + t1.w, 0.f), wv.y, a3);
        a0 = fmaf(fmaxf(sv.z + t2.x, 0.f), wv.z, a0);
        a1 = fmaf(fmaxf(sv.z + t2.y, 0.f), wv.z, a1);
        a2 = fmaf(fmaxf(sv.z + t2.z, 0.f), wv.z, a2);
        a3 = fmaf(fmaxf(sv.z + t2.w, 0.f), wv.z, a3);
        a0 = fmaf(fmaxf(sv.w + t3.x, 0.f), wv.w, a0);
        a1 = fmaf(fmaxf(sv.w + t3.y, 0.f), wv.w, a1);
        a2 = fmaf(fmaxf(sv.w + t3.z, 0.f), wv.w, a2);
        a3 = fmaf(fmaxf(sv.w + t3.w, 0.f), wv.w, a3);
    }
    float bz = bs2[0];
    int i = i0 + ti;
    float accs[4] = {a0, a1, a2, a3};
    #pragma unroll
    for (int jj = 0; jj < 4; jj++) {
        int j = j0 + tjb + jj;
        float sc = 1.f / (1.f + __expf(-(accs[jj] + bz)));
        float a  = (sc > 0.1f && i != j) ? sc : 0.f;
        g_adj[((size_t)b * Nn + i) * Nn + j] = a;
    }
}

// ---------------- stage 3/4: batched TF32 GEMMs, split-K=2, 32x32 warp tiles --
// PHASE=0: p_kh = adj[:, kslice] @ adj[kslice, :]
// PHASE=1: q_kh = (p0+p1)[:, kslice] @ adj[kslice, :]
#define TM 64
#define TN 64
#define TK 32
#define KH 256      // K per split half
#define ASTR 36     // A-frag banks 4*gid + tig : bijective
#define BSTR 72     // B-frag banks 8*tig + gid : bijective

__device__ __forceinline__ unsigned f2tf32(float x) {
    unsigned r;
    asm("cvt.rna.tf32.f32 %0, %1;" : "=r"(r) : "f"(x));
    return r;
}

__device__ __forceinline__ void mma_tf32(float* d, const unsigned* a,
                                         const unsigned* b, const float* c) {
    asm volatile(
        "mma.sync.aligned.m16n8k8.row.col.f32.tf32.tf32.f32 "
        "{%0,%1,%2,%3}, {%4,%5,%6,%7}, {%8,%9}, {%10,%11,%12,%13};\n"
        : "=f"(d[0]), "=f"(d[1]), "=f"(d[2]), "=f"(d[3])
        : "r"(a[0]), "r"(a[1]), "r"(a[2]), "r"(a[3]),
          "r"(b[0]), "r"(b[1]),
          "f"(c[0]), "f"(c[1]), "f"(c[2]), "f"(c[3]));
}

__device__ __forceinline__ float4 cvt4(float4 v) {
    float4 t;
    t.x = __uint_as_float(f2tf32(v.x));
    t.y = __uint_as_float(f2tf32(v.y));
    t.z = __uint_as_float(f2tf32(v.z));
    t.w = __uint_as_float(f2tf32(v.w));
    return t;
}

template <int PHASE>
__global__ __launch_bounds__(128) void k_mma()
{
    int z  = blockIdx.z;
    int b  = z >> 1;
    int kh = z & 1;
    int kbase = kh * KH;

    const float* A1 = (PHASE ? g_p0 : g_adj) + (size_t)b * Nn * Nn;
    const float* A2 = g_p1 + (size_t)b * Nn * Nn;   // used only if PHASE
    const float* Bp = g_adj + (size_t)b * Nn * Nn;
    float* Ob = (PHASE ? (kh ? g_q1 : g_q0) : (kh ? g_p1 : g_p0))
                + (size_t)b * Nn * Nn;

    __shared__ float As[2][TM * ASTR];
    __shared__ float Bs[2][TK * BSTR];

    int tid  = threadIdx.x;
    int m0   = blockIdx.y * TM, n0 = blockIdx.x * TN;
    int warpId = tid >> 5, lane = tid & 31;
    int wm  = (warpId & 1) * 32;
    int wn  = (warpId >> 1) * 32;
    int gid = lane >> 2, tig = lane & 3;

    // staging: A tile 64x32 (4 float4/thread), B tile 32x64 (4 float4/thread)
    int arow = tid >> 3, ac4 = (tid & 7) * 4;     // rows arow + p*16
    int brow = tid >> 4, bc4 = (tid & 15) * 4;    // rows brow + p*8

    const float* agp  = A1 + (size_t)(m0 + arow) * Nn + kbase + ac4;
    const float* agp2 = A2 + (size_t)(m0 + arow) * Nn + kbase + ac4;
    const float* bgp  = Bp + (size_t)(kbase + brow) * Nn + n0 + bc4;

    float4 ra[4], rb[4];
    #pragma unroll
    for (int p = 0; p < 4; p++) {
        ra[p] = *(const float4*)(agp + (size_t)p * 16 * Nn);
        if (PHASE) {
            float4 e = *(const float4*)(agp2 + (size_t)p * 16 * Nn);
            ra[p].x += e.x; ra[p].y += e.y; ra[p].z += e.z; ra[p].w += e.w;
        }
        rb[p] = *(const float4*)(bgp + (size_t)p * 8 * Nn);
    }

    #pragma unroll
    for (int p = 0; p < 4; p++) {
        *(float4*)(As[0] + (arow + p * 16) * ASTR + ac4) = cvt4(ra[p]);
        *(float4*)(Bs[0] + (brow + p * 8) * BSTR + bc4)  = cvt4(rb[p]);
    }
    __syncthreads();

    float acc[2][4][4];
    #pragma unroll
    for (int i = 0; i < 2; i++)
        #pragma unroll
        for (int j = 0; j < 4; j++)
            #pragma unroll
            for (int r = 0; r < 4; r++) acc[i][j][r] = 0.f;

    #pragma unroll 1
    for (int kt = 0; kt < KH / TK; kt++) {
        int cur = kt & 1;
        if (kt < KH / TK - 1) {                   // prefetch next panel
            int k0 = (kt + 1) * TK;
            #pragma unroll
            for (int p = 0; p < 4; p++) {
                ra[p] = *(const float4*)(agp + k0 + (size_t)p * 16 * Nn);
                if (PHASE) {
                    float4 e = *(const float4*)(agp2 + k0 + (size_t)p * 16 * Nn);
                    ra[p].x += e.x; ra[p].y += e.y; ra[p].z += e.z; ra[p].w += e.w;
                }
                rb[p] = *(const float4*)(bgp + (size_t)k0 * Nn + (size_t)p * 8 * Nn);
            }
        }

        const float* Ac = As[cur];
        const float* Bc = Bs[cur];
        #pragma unroll
        for (int ks = 0; ks < 4; ks++) {
            int kb = ks * 8;
            unsigned af[2][4], bf[4][2];
            #pragma unroll
            for (int mt = 0; mt < 2; mt++) {
                int r0 = wm + mt * 16 + gid;
                af[mt][0] = __float_as_uint(Ac[r0 * ASTR + kb + tig]);
                af[mt][1] = __float_as_uint(Ac[(r0 + 8) * ASTR + kb + tig]);
                af[mt][2] = __float_as_uint(Ac[r0 * ASTR + kb + tig + 4]);
                af[mt][3] = __float_as_uint(Ac[(r0 + 8) * ASTR + kb + tig + 4]);
            }
            #pragma unroll
            for (int nt = 0; nt < 4; nt++) {
                int c0 = wn + nt * 8 + gid;
                bf[nt][0] = __float_as_uint(Bc[(kb + tig) * BSTR + c0]);
                bf[nt][1] = __float_as_uint(Bc[(kb + tig + 4) * BSTR + c0]);
            }
            #pragma unroll
            for (int mt = 0; mt < 2; mt++)
                #pragma unroll
                for (int nt = 0; nt < 4; nt++)
                    mma_tf32(acc[mt][nt], af[mt], bf[nt], acc[mt][nt]);
        }

        if (kt < KH / TK - 1) {
            int nxt = cur ^ 1;
            #pragma unroll
            for (int p = 0; p < 4; p++) {
                *(float4*)(As[nxt] + (arow + p * 16) * ASTR + ac4) = cvt4(ra[p]);
                *(float4*)(Bs[nxt] + (brow + p * 8) * BSTR + bc4)  = cvt4(rb[p]);
            }
        }
        __syncthreads();
    }

    // epilogue: write partials (no fusion here)
    #pragma unroll
    for (int mt = 0; mt < 2; mt++) {
        #pragma unroll
        for (int nt = 0; nt < 4; nt++) {
            int row = m0 + wm + mt * 16 + gid;
            int col = n0 + wn + nt * 8 + 2 * tig;
            #pragma unroll
            for (int h = 0; h < 2; h++) {
                int r = row + h * 8;
                *(float2*)(Ob + (size_t)r * Nn + col) =
                    make_float2(acc[mt][nt][2 * h + 0], acc[mt][nt][2 * h + 1]);
            }
        }
    }
}

// ---------------- stage 5: combine + per-batch max ----------------
__global__ __launch_bounds__(256) void k_enhance(float* __restrict__ out)
{
    __shared__ float wmax[8];
    int idx = blockIdx.x * 256 + threadIdx.x;     // over B*N*N/4 float4
    int b = idx >> 16;                            // N*N/4 = 2^16 per batch

    float4 a  = ((const float4*)g_adj)[idx];
    float4 p0 = ((const float4*)g_p0)[idx];
    float4 p1 = ((const float4*)g_p1)[idx];
    float4 q0 = ((const float4*)g_q0)[idx];
    float4 q1 = ((const float4*)g_q1)[idx];

    float4 e;
    e.x = a.x + 0.5f * (p0.x + p1.x) + 0.25f * (q0.x + q1.x);
    e.y = a.y + 0.5f * (p0.y + p1.y) + 0.25f * (q0.y + q1.y);
    e.z = a.z + 0.5f * (p0.z + p1.z) + 0.25f * (q0.z + q1.z);
    e.w = a.w + 0.5f * (p0.w + p1.w) + 0.25f * (q0.w + q1.w);
    ((float4*)out)[idx] = e;

    float lmax = fmaxf(fmaxf(e.x, e.y), fmaxf(e.z, e.w));
    #pragma unroll
    for (int s = 16; s > 0; s >>= 1)
        lmax = fmaxf(lmax, __shfl_xor_sync(0xFFFFFFFFu, lmax, s));
    int warpId = threadIdx.x >> 5, lane = threadIdx.x & 31;
    if (lane == 0) wmax[warpId] = lmax;
    __syncthreads();
    if (threadIdx.x == 0) {
        float m = wmax[0];
        #pragma unroll
        for (int i = 1; i < 8; i++) m = fmaxf(m, wmax[i]);
        atomicMax(&g_maxbits[b], __float_as_uint(m));
    }
}

// ---------------- stage 6: normalize (float4) ----------------
__global__ void k_norm(float* __restrict__ out)
{
    int idx = blockIdx.x * 256 + threadIdx.x;
    int b = idx >> 16;
    float mx = __uint_as_float(g_maxbits[b]);
    float inv = 1.f / (mx + 1e-8f);
    float4 v = ((const float4*)out)[idx];
    v.x *= inv; v.y *= inv; v.z *= inv; v.w *= inv;
    ((float4*)out)[idx] = v;
}

// ---------------- launch ----------------
extern "C" void kernel_launch(void* const* d_in, const int* in_sizes, int n_in,
                              void* d_out, int out_size)
{
    const float* x   = (const float*)d_in[0];
    const float* W1  = (const float*)d_in[1];
    const float* b1  = (const float*)d_in[2];
    const float* W2  = (const float*)d_in[3];
    const float* b2  = (const float*)d_in[4];
    const float* Ws1 = (const float*)d_in[5];
    const float* bs1 = (const float*)d_in[6];
    const float* Ws2 = (const float*)d_in[7];
    const float* bs2 = (const float*)d_in[8];
    float* out = (float*)d_out;

    k_encode<<<(Bb * Nn) / 16, 256>>>(x, W1, b1, W2, b2, Ws1, bs1);
    k_score<<<dim3(Nn / 32, Nn / 32, Bb), dim3(8, 32)>>>(Ws2, bs2);
    k_mma<0><<<dim3(Nn / TN, Nn / TM, Bb * 2), 128>>>();
    k_mma<1><<<dim3(Nn / TN, Nn / TM, Bb * 2), 128>>>();
    k_enhance<<<(Bb * Nn * Nn) / 1024, 256>>>(out);
    k_norm<<<(Bb * Nn * Nn) / 1024, 256>>>(out);
}

// round 10
// speedup vs baseline: 1.6095x; 1.0500x over previous
#include <cuda_runtime.h>

#define Bb 4
#define Tt 12
#define Nn 512
#define Dd 128
#define Ll 4
#define Hh 64

typedef unsigned long long ull;

// ---------------- scratch (no allocation allowed) ----------------
__device__ float g_src[Bb * Nn * Dd];     // src_proj
__device__ float g_tgt[Bb * Nn * Dd];     // tgt_proj + bs1 folded in
__device__ float g_adj[Bb * Nn * Nn];     // thresholded adjacency
__device__ float g_p0[Bb * Nn * Nn];      // a2 partial (k-half 0)
__device__ float g_p1[Bb * Nn * Nn];      // a2 partial (k-half 1)
__device__ float g_q0[Bb * Nn * Nn];      // a3 partial (k-half 0)
__device__ float g_q1[Bb * Nn * Nn];      // a3 partial (k-half 1)
__device__ unsigned g_maxbits[Bb];        // per-batch max (float bits, all >= 0)

// ---------------- stage 1: lag encoders + mean + projections ----------------
__global__ __launch_bounds__(256) void k_encode(
    const float* __restrict__ x,
    const float* __restrict__ W1, const float* __restrict__ b1,
    const float* __restrict__ W2, const float* __restrict__ b2,
    const float* __restrict__ Ws1, const float* __restrict__ bs1)
{
    __shared__ float xl[16 * 512];   // [(r*4+l)*128 + d]; later reused as agg[r*128+d]
    __shared__ float hs[16 * 256];   // [r*256 + l*64 + j]

    int tid = threadIdx.x;
    if (blockIdx.x == 0 && tid < Bb) g_maxbits[tid] = 0u;   // folded k_init

    int bn0 = blockIdx.x * 16;           // first global row (b*N + n)
    int b   = bn0 >> 9;
    int n0  = bn0 & (Nn - 1);

    #pragma unroll
    for (int i = 0; i < 32; i++) {
        int e  = tid + i * 256;
        int d  = e & 127;
        int rl = e >> 7;
        int r  = rl >> 2, l = rl & 3;
        xl[e] = x[(((b * Tt) + (Tt - 1 - l)) * Nn + (n0 + r)) * Dd + d];
    }
    __syncthreads();

    {
        int l = tid >> 6, j = tid & 63;
        float acc[16];
        float bb = b1[l * Hh + j];
        #pragma unroll
        for (int r = 0; r < 16; r++) acc[r] = bb;
        const float* w1 = W1 + (size_t)l * Dd * Hh + j;
        for (int d = 0; d < Dd; d++) {
            float w = w1[d * Hh];
            #pragma unroll
            for (int r = 0; r < 16; r++)
                acc[r] = fmaf(xl[(r * 4 + l) * 128 + d], w, acc[r]);
        }
        #pragma unroll
        for (int r = 0; r < 16; r++)
            hs[r * 256 + tid] = fmaxf(acc[r], 0.f);
    }
    __syncthreads();

    {
        int d = tid & 127, halfr = tid >> 7;
        float bbar = 0.f;
        #pragma unroll
        for (int l = 0; l < Ll; l++) bbar += b2[l * Dd + d];
        bbar *= 0.25f;
        float acc[8];
        #pragma unroll
        for (int r = 0; r < 8; r++) acc[r] = 0.f;
        for (int o = 0; o < Ll * Hh; o++) {
            float w = W2[(size_t)o * Dd + d];
            #pragma unroll
            for (int r = 0; r < 8; r++)
                acc[r] = fmaf(hs[(halfr * 8 + r) * 256 + o], w, acc[r]);
        }
        #pragma unroll
        for (int r = 0; r < 8; r++)
            xl[(halfr * 8 + r) * 128 + d] = fmaf(acc[r], 0.25f, bbar);
    }
    __syncthreads();

    {
        int dcol = tid & 127;
        int half = tid >> 7;                 // 0 = src, 1 = tgt
        float acc[16];
        float binit = half ? bs1[dcol] : 0.f;
        #pragma unroll
        for (int r = 0; r < 16; r++) acc[r] = binit;
        const float* ws = Ws1 + (size_t)half * Dd * Dd + dcol;
        for (int dd = 0; dd < Dd; dd++) {
            float w = ws[dd * Dd];
            #pragma unroll
            for (int r = 0; r < 16; r++)
                acc[r] = fmaf(xl[r * 128 + dd], w, acc[r]);
        }
        float* dst = half ? g_tgt : g_src;
        #pragma unroll
        for (int r = 0; r < 16; r++)
            dst[(size_t)(bn0 + r) * Dd + dcol] = acc[r];
    }
}

// ---------------- stage 2: pairwise scorer (packed f32x2) ----------------
// block (4,32): ti = threadIdx.y, threadIdx.x covers 8 j's (4 packed pairs)
__device__ __forceinline__ ull pk2(float x) {
    ull r;
    asm("mov.b64 %0, {%1, %1};" : "=l"(r) : "f"(x));
    return r;
}

// acc += max(t2 + s2, 0) * w2   (per 32-bit lane)
__device__ __forceinline__ void pstep(ull& acc, ull t2, ull s2, ull w2) {
    asm("{\n\t"
        ".reg .b64 t;\n\t"
        ".reg .f32 lo, hi;\n\t"
        "add.rn.f32x2 t, %1, %2;\n\t"
        "mov.b64 {lo, hi}, t;\n\t"
        "max.f32 lo, lo, 0f00000000;\n\t"
        "max.f32 hi, hi, 0f00000000;\n\t"
        "mov.b64 t, {lo, hi};\n\t"
        "fma.rn.f32x2 %0, t, %3, %0;\n\t"
        "}"
        : "+l"(acc) : "l"(t2), "l"(s2), "l"(w2));
}

__global__ __launch_bounds__(128) void k_score(
    const float* __restrict__ Ws2, const float* __restrict__ bs2)
{
    __shared__ float st [32][132];   // [i][d]
    __shared__ float ttT[128][36];   // [d][j]
    __shared__ float w4[128];

    int b  = blockIdx.z;
    int i0 = blockIdx.y * 32, j0 = blockIdx.x * 32;
    int tx = threadIdx.x, ty = threadIdx.y;
    int tid = ty * 4 + tx;

    // st: 1024 float4 loads
    #pragma unroll
    for (int it = 0; it < 8; it++) {
        int e = tid + it * 128;
        int r = e >> 5, c4 = (e & 31) * 4;
        *(float4*)&st[r][c4] =
            *(const float4*)&g_src[(size_t)(b * Nn + i0 + r) * Dd + c4];
    }
    // ttT: 4x4 register-transposed blocks (conflict-free STS.128)
    #pragma unroll
    for (int it = 0; it < 2; it++) {
        int e  = tid + it * 128;          // block index 0..255
        int j4 = (e & 7) * 4, d4 = (e >> 3) * 4;
        const float* base = g_tgt + (size_t)(b * Nn + j0 + j4) * Dd + d4;
        float4 r0 = *(const float4*)(base);
        float4 r1 = *(const float4*)(base + Dd);
        float4 r2 = *(const float4*)(base + 2 * Dd);
        float4 r3 = *(const float4*)(base + 3 * Dd);
        *(float4*)&ttT[d4 + 0][j4] = make_float4(r0.x, r1.x, r2.x, r3.x);
        *(float4*)&ttT[d4 + 1][j4] = make_float4(r0.y, r1.y, r2.y, r3.y);
        *(float4*)&ttT[d4 + 2][j4] = make_float4(r0.z, r1.z, r2.z, r3.z);
        *(float4*)&ttT[d4 + 3][j4] = make_float4(r0.w, r1.w, r2.w, r3.w);
    }
    w4[tid] = Ws2[tid];
    __syncthreads();

    int ti = ty;
    int jb = tx * 8;
    ull acc01 = 0, acc23 = 0, acc45 = 0, acc67 = 0;

    #pragma unroll 4
    for (int d = 0; d < Dd; d += 4) {
        float4 sv = *(const float4*)&st[ti][d];
        float4 wv = *(const float4*)&w4[d];
        float svv[4] = {sv.x, sv.y, sv.z, sv.w};
        float wvv[4] = {wv.x, wv.y, wv.z, wv.w};
        #pragma unroll
        for (int q = 0; q < 4; q++) {
            ulonglong2 ta = *(const ulonglong2*)&ttT[d + q][jb];
            ulonglong2 tb = *(const ulonglong2*)&ttT[d + q][jb + 4];
            ull s2 = pk2(svv[q]);
            ull w2 = pk2(wvv[q]);
            pstep(acc01, ta.x, s2, w2);
            pstep(acc23, ta.y, s2, w2);
            pstep(acc45, tb.x, s2, w2);
            pstep(acc67, tb.y, s2, w2);
        }
    }

    float a[8];
    asm("mov.b64 {%0, %1}, %2;" : "=f"(a[0]), "=f"(a[1]) : "l"(acc01));
    asm("mov.b64 {%0, %1}, %2;" : "=f"(a[2]), "=f"(a[3]) : "l"(acc23));
    asm("mov.b64 {%0, %1}, %2;" : "=f"(a[4]), "=f"(a[5]) : "l"(acc45));
    asm("mov.b64 {%0, %1}, %2;" : "=f"(a[6]), "=f"(a[7]) : "l"(acc67));

    float bz = bs2[0];
    int i = i0 + ti;
    float o[8];
    #pragma unroll
    for (int jj = 0; jj < 8; jj++) {
        int j = j0 + jb + jj;
        float sc = 1.f / (1.f + __expf(-(a[jj] + bz)));
        o[jj] = (sc > 0.1f && i != j) ? sc : 0.f;
    }
    float* dst = g_adj + ((size_t)b * Nn + i) * Nn + j0 + jb;
    *(float4*)(dst)     = make_float4(o[0], o[1], o[2], o[3]);
    *(float4*)(dst + 4) = make_float4(o[4], o[5], o[6], o[7]);
}

// ---------------- stage 3/4: TF32 GEMMs, split-K=2, cp.async staging -------
// PHASE=0: p_kh = adj[:, kslice] @ adj[kslice, :]
// PHASE=1: q_kh = (p0+p1)[:, kslice] @ adj[kslice, :]
// Raw fp32 bits fed as tf32 (HW ignores low mantissa bits).
#define TM 64
#define TN 64
#define TK 32
#define KH 256
#define ASTR 36
#define BSTR 72

__device__ __forceinline__ void mma_tf32(float* d, const unsigned* a,
                                         const unsigned* b, const float* c) {
    asm volatile(
        "mma.sync.aligned.m16n8k8.row.col.f32.tf32.tf32.f32 "
        "{%0,%1,%2,%3}, {%4,%5,%6,%7}, {%8,%9}, {%10,%11,%12,%13};\n"
        : "=f"(d[0]), "=f"(d[1]), "=f"(d[2]), "=f"(d[3])
        : "r"(a[0]), "r"(a[1]), "r"(a[2]), "r"(a[3]),
          "r"(b[0]), "r"(b[1]),
          "f"(c[0]), "f"(c[1]), "f"(c[2]), "f"(c[3]));
}

__device__ __forceinline__ void cp16(unsigned dst, const void* src) {
    asm volatile("cp.async.ca.shared.global [%0], [%1], 16;"
                 :: "r"(dst), "l"(src));
}
__device__ __forceinline__ void cp_commit() {
    asm volatile("cp.async.commit_group;" ::: "memory");
}
__device__ __forceinline__ void cp_wait1() {
    asm volatile("cp.async.wait_group 1;" ::: "memory");
}

template <int PHASE>
__global__ __launch_bounds__(128) void k_mma()
{
    int z  = blockIdx.z;
    int b  = z >> 1;
    int kh = z & 1;
    int kbase = kh * KH;

    const float* A1 = (PHASE ? g_p0 : g_adj) + (size_t)b * Nn * Nn;
    const float* A2 = g_p1 + (size_t)b * Nn * Nn;
    const float* Bp = g_adj + (size_t)b * Nn * Nn;
    float* Ob = (PHASE ? (kh ? g_q1 : g_q0) : (kh ? g_p1 : g_p0))
                + (size_t)b * Nn * Nn;

    __shared__ float As[2][TM * ASTR];
    __shared__ float Bs[2][TK * BSTR];

    int tid  = threadIdx.x;
    int m0   = blockIdx.y * TM, n0 = blockIdx.x * TN;
    int warpId = tid >> 5, lane = tid & 31;
    int wm  = (warpId & 1) * 32;
    int wn  = (warpId >> 1) * 32;
    int gid = lane >> 2, tig = lane & 3;

    int arow = tid >> 3, ac4 = (tid & 7) * 4;     // A rows arow + p*16
    int brow = tid >> 4, bc4 = (tid & 15) * 4;    // B rows brow + p*8

    const float* agp  = A1 + (size_t)(m0 + arow) * Nn + kbase + ac4;
    const float* agp2 = A2 + (size_t)(m0 + arow) * Nn + kbase + ac4;
    const float* bgp  = Bp + (size_t)(kbase + brow) * Nn + n0 + bc4;

    unsigned sA[2], sB[2];
    sA[0] = (unsigned)__cvta_generic_to_shared(&As[0][0]);
    sA[1] = (unsigned)__cvta_generic_to_shared(&As[1][0]);
    sB[0] = (unsigned)__cvta_generic_to_shared(&Bs[0][0]);
    sB[1] = (unsigned)__cvta_generic_to_shared(&Bs[1][0]);
    unsigned aoff[4], boff[4];
    #pragma unroll
    for (int p = 0; p < 4; p++) {
        aoff[p] = ((arow + p * 16) * ASTR + ac4) * 4u;
        boff[p] = ((brow + p * 8) * BSTR + bc4) * 4u;
    }

    float4 ra[4];

    // ---- initial stage into buffer 0 ----
    if (PHASE == 0) {
        #pragma unroll
        for (int p = 0; p < 4; p++) cp16(sA[0] + aoff[p], agp + (size_t)p * 16 * Nn);
    } else {
        #pragma unroll
        for (int p = 0; p < 4; p++) {
            ra[p] = *(const float4*)(agp + (size_t)p * 16 * Nn);
            float4 e = *(const float4*)(agp2 + (size_t)p * 16 * Nn);
            ra[p].x += e.x; ra[p].y += e.y; ra[p].z += e.z; ra[p].w += e.w;
        }
    }
    #pragma unroll
    for (int p = 0; p < 4; p++) cp16(sB[0] + boff[p], bgp + (size_t)p * 8 * Nn);
    cp_commit();
    if (PHASE == 1) {
        #pragma unroll
        for (int p = 0; p < 4; p++)
            *(float4*)(As[0] + (arow + p * 16) * ASTR + ac4) = ra[p];
    }

    float acc[2][4][4];
    #pragma unroll
    for (int i = 0; i < 2; i++)
        #pragma unroll
        for (int j = 0; j < 4; j++)
            #pragma unroll
            for (int r = 0; r < 4; r++) acc[i][j][r] = 0.f;

    const int NT = KH / TK;
    #pragma unroll 1
    for (int kt = 0; kt < NT; kt++) {
        int cur = kt & 1, nxt = cur ^ 1;
        bool has = (kt + 1 < NT);
        int k0n = (kt + 1) * TK;

        if (has) {
            if (PHASE == 0) {
                #pragma unroll
                for (int p = 0; p < 4; p++)
                    cp16(sA[nxt] + aoff[p], agp + k0n + (size_t)p * 16 * Nn);
            }
            #pragma unroll
            for (int p = 0; p < 4; p++)
                cp16(sB[nxt] + boff[p], bgp + (size_t)k0n * Nn + (size_t)p * 8 * Nn);
            cp_commit();
            if (PHASE == 1) {
                #pragma unroll
                for (int p = 0; p < 4; p++) {
                    ra[p] = *(const float4*)(agp + k0n + (size_t)p * 16 * Nn);
                    float4 e = *(const float4*)(agp2 + k0n + (size_t)p * 16 * Nn);
                    ra[p].x += e.x; ra[p].y += e.y; ra[p].z += e.z; ra[p].w += e.w;
                }
            }
        } else {
            cp_commit();           // empty group keeps wait count aligned
        }
        cp_wait1();
        __syncthreads();

        const float* Ac = As[cur];
        const float* Bc = Bs[cur];
        #pragma unroll
        for (int ks = 0; ks < 4; ks++) {
            int kb = ks * 8;
            unsigned af[2][4], bf[4][2];
            #pragma unroll
            for (int mt = 0; mt < 2; mt++) {
                int r0 = wm + mt * 16 + gid;
                af[mt][0] = __float_as_uint(Ac[r0 * ASTR + kb + tig]);
                af[mt][1] = __float_as_uint(Ac[(r0 + 8) * ASTR + kb + tig]);
                af[mt][2] = __float_as_uint(Ac[r0 * ASTR + kb + tig + 4]);
                af[mt][3] = __float_as_uint(Ac[(r0 + 8) * ASTR + kb + tig + 4]);
            }
            #pragma unroll
            for (int nt = 0; nt < 4; nt++) {
                int c0 = wn + nt * 8 + gid;
                bf[nt][0] = __float_as_uint(Bc[(kb + tig) * BSTR + c0]);
                bf[nt][1] = __float_as_uint(Bc[(kb + tig + 4) * BSTR + c0]);
            }
            #pragma unroll
            for (int mt = 0; mt < 2; mt++)
                #pragma unroll
                for (int nt = 0; nt < 4; nt++)
                    mma_tf32(acc[mt][nt], af[mt], bf[nt], acc[mt][nt]);
        }

        if (PHASE == 1 && has) {
            #pragma unroll
            for (int p = 0; p < 4; p++)
                *(float4*)(As[nxt] + (arow + p * 16) * ASTR + ac4) = ra[p];
        }
        __syncthreads();
    }

    #pragma unroll
    for (int mt = 0; mt < 2; mt++) {
        #pragma unroll
        for (int nt = 0; nt < 4; nt++) {
            int row = m0 + wm + mt * 16 + gid;
            int col = n0 + wn + nt * 8 + 2 * tig;
            #pragma unroll
            for (int h = 0; h < 2; h++) {
                int r = row + h * 8;
                *(float2*)(Ob + (size_t)r * Nn + col) =
                    make_float2(acc[mt][nt][2 * h + 0], acc[mt][nt][2 * h + 1]);
            }
        }
    }
}

// ---------------- stage 5: combine + per-batch max ----------------
__global__ __launch_bounds__(256) void k_enhance(float* __restrict__ out)
{
    __shared__ float wmax[8];
    int idx = blockIdx.x * 256 + threadIdx.x;     // over B*N*N/4 float4
    int b = idx >> 16;

    float4 a  = ((const float4*)g_adj)[idx];
    float4 p0 = ((const float4*)g_p0)[idx];
    float4 p1 = ((const float4*)g_p1)[idx];
    float4 q0 = ((const float4*)g_q0)[idx];
    float4 q1 = ((const float4*)g_q1)[idx];

    float4 e;
    e.x = a.x + 0.5f * (p0.x + p1.x) + 0.25f * (q0.x + q1.x);
    e.y = a.y + 0.5f * (p0.y + p1.y) + 0.25f * (q0.y + q1.y);
    e.z = a.z + 0.5f * (p0.z + p1.z) + 0.25f * (q0.z + q1.z);
    e.w = a.w + 0.5f * (p0.w + p1.w) + 0.25f * (q0.w + q1.w);
    ((float4*)out)[idx] = e;

    float lmax = fmaxf(fmaxf(e.x, e.y), fmaxf(e.z, e.w));
    #pragma unroll
    for (int s = 16; s > 0; s >>= 1)
        lmax = fmaxf(lmax, __shfl_xor_sync(0xFFFFFFFFu, lmax, s));
    int warpId = threadIdx.x >> 5, lane = threadIdx.x & 31;
    if (lane == 0) wmax[warpId] = lmax;
    __syncthreads();
    if (threadIdx.x == 0) {
        float m = wmax[0];
        #pragma unroll
        for (int i = 1; i < 8; i++) m = fmaxf(m, wmax[i]);
        atomicMax(&g_maxbits[b], __float_as_uint(m));
    }
}

// ---------------- stage 6: normalize (float4) ----------------
__global__ void k_norm(float* __restrict__ out)
{
    int idx = blockIdx.x * 256 + threadIdx.x;
    int b = idx >> 16;
    float mx = __uint_as_float(g_maxbits[b]);
    float inv = 1.f / (mx + 1e-8f);
    float4 v = ((const float4*)out)[idx];
    v.x *= inv; v.y *= inv; v.z *= inv; v.w *= inv;
    ((float4*)out)[idx] = v;
}

// ---------------- launch ----------------
extern "C" void kernel_launch(void* const* d_in, const int* in_sizes, int n_in,
                              void* d_out, int out_size)
{
    const float* x   = (const float*)d_in[0];
    const float* W1  = (const float*)d_in[1];
    const float* b1  = (const float*)d_in[2];
    const float* W2  = (const float*)d_in[3];
    const float* b2  = (const float*)d_in[4];
    const float* Ws1 = (const float*)d_in[5];
    const float* bs1 = (const float*)d_in[6];
    const float* Ws2 = (const float*)d_in[7];
    const float* bs2 = (const float*)d_in[8];
    float* out = (float*)d_out;

    k_encode<<<(Bb * Nn) / 16, 256>>>(x, W1, b1, W2, b2, Ws1, bs1);
    k_score<<<dim3(Nn / 32, Nn / 32, Bb), dim3(4, 32)>>>(Ws2, bs2);
    k_mma<0><<<dim3(Nn / TN, Nn / TM, Bb * 2), 128>>>();
    k_mma<1><<<dim3(Nn / TN, Nn / TM, Bb * 2), 128>>>();
    k_enhance<<<(Bb * Nn * Nn) / 1024, 256>>>(out);
    k_norm<<<(Bb * Nn * Nn) / 1024, 256>>>(out);
}